// round 15
// baseline (speedup 1.0000x reference)
#include <cuda_runtime.h>
#include <cuda_bf16.h>
#include <cstdint>

#define BATCH 16
#define NQ 2048
#define NK 2048
#define DIM 128
#define SCALE 1.153f
#define INV_KEEP (1.0f / 0.7f)
#define KEEP_THRESH 0xB3333400u

// ---------------- scratch ---------------------------------------------------
static __device__ __nv_bfloat16 g_x1h[(size_t)BATCH * NQ * DIM];
static __device__ __nv_bfloat16 g_x1l[(size_t)BATCH * NQ * DIM];
static __device__ __nv_bfloat16 g_x2h[(size_t)BATCH * NK * DIM];
static __device__ __nv_bfloat16 g_x2l[(size_t)BATCH * NK * DIM];

// ---------------- helpers ---------------------------------------------------
__device__ __forceinline__ uint32_t smem_u32(const void* p) {
    uint32_t a;
    asm("{ .reg .u64 t; cvta.to.shared.u64 t, %1; cvt.u32.u64 %0, t; }" : "=r"(a) : "l"(p));
    return a;
}
__device__ __forceinline__ void mma16816(float* d, const uint32_t* a, const uint32_t* b) {
    asm volatile(
        "mma.sync.aligned.m16n8k16.row.col.f32.bf16.bf16.f32 "
        "{%0,%1,%2,%3}, {%4,%5,%6,%7}, {%8,%9}, {%0,%1,%2,%3};"
        : "+f"(d[0]), "+f"(d[1]), "+f"(d[2]), "+f"(d[3])
        : "r"(a[0]), "r"(a[1]), "r"(a[2]), "r"(a[3]), "r"(b[0]), "r"(b[1]));
}
__device__ __forceinline__ void ldsm_x4(uint32_t* r, uint32_t addr) {
    asm volatile("ldmatrix.sync.aligned.m8n8.x4.shared.b16 {%0,%1,%2,%3}, [%4];"
                 : "=r"(r[0]), "=r"(r[1]), "=r"(r[2]), "=r"(r[3]) : "r"(addr));
}
__device__ __forceinline__ void ldsm_x4_t(uint32_t* r, uint32_t addr) {
    asm volatile("ldmatrix.sync.aligned.m8n8.x4.trans.shared.b16 {%0,%1,%2,%3}, [%4];"
                 : "=r"(r[0]), "=r"(r[1]), "=r"(r[2]), "=r"(r[3]) : "r"(addr));
}
__device__ __forceinline__ uint32_t pack_bf16(float lo, float hi) {
    uint32_t r;
    asm("cvt.rn.bf16x2.f32 %0, %1, %2;" : "=r"(r) : "f"(hi), "f"(lo));
    return r;
}
__device__ __forceinline__ void cp_async16(uint32_t dst, const void* src) {
    asm volatile("cp.async.cg.shared.global [%0], [%1], 16;" :: "r"(dst), "l"(src));
}
#define CP_COMMIT() asm volatile("cp.async.commit_group;" ::: "memory")

// bf16 tile with 256B/row (128 cols), XOR swizzle on 16B granules
__device__ __forceinline__ uint32_t tile_addr(uint32_t base, int row, int col) {
    return base + row * 256 + ((((col >> 3) ^ (row & 7)) << 4));
}
// 64-row tile sync load (x1, 128 threads): 1024 granules, 8 per thread
__device__ __forceinline__ void load_tile64(uint32_t dst, const __nv_bfloat16* __restrict__ src,
                                            int ld) {
    const int tid = threadIdx.x;
#pragma unroll
    for (int i = 0; i < 8; i++) {
        int idx = tid + i * 128;
        int row = idx >> 4, g = idx & 15;
        uint4 v = *(const uint4*)(src + (size_t)row * ld + g * 8);
        uint32_t a = dst + row * 256 + ((g ^ (row & 7)) << 4);
        asm volatile("st.shared.v4.b32 [%0], {%1,%2,%3,%4};"
                     :: "r"(a), "r"(v.x), "r"(v.y), "r"(v.z), "r"(v.w));
    }
}
// 64-row tile async copy (x2 k-tile, 128 threads): 1024 granules, 8 per thread
__device__ __forceinline__ void cp_tile64(uint32_t dst, const __nv_bfloat16* __restrict__ src,
                                          int ld) {
    const int tid = threadIdx.x;
#pragma unroll
    for (int i = 0; i < 8; i++) {
        int idx = tid + i * 128;
        int row = idx >> 4, g = idx & 15;
        cp_async16(dst + row * 256 + ((g ^ (row & 7)) << 4), src + (size_t)row * ld + g * 8);
    }
}

#define SM_X1H 0
#define SM_X1L 16384
// each X2 buffer: hi tile (16KB) + lo tile (16KB)
#define SM_X2(buf) (32768 + (buf) * 32768)
#define SMEM_BYTES (32768 + 2 * 32768)  // 96KB -> 2 CTAs/SM

// ---------------------------------------------------------------------------
// threefry2x32, jax partitionable semantics (verified exact)
// ---------------------------------------------------------------------------
__device__ __forceinline__ unsigned rotl32(unsigned x, int r) { return __funnelshift_l(x, x, r); }

__device__ __forceinline__ unsigned tf_keep(unsigned i) {
    const unsigned ks0 = 0u, ks1 = 42u, ks2 = 0x1BD11BDAu ^ ks0 ^ ks1;
    unsigned x0 = ks0, x1 = i + ks1;
#define TF_ROUND(r) { x0 += x1; x1 = rotl32(x1, (r)); x1 ^= x0; }
    TF_ROUND(13) TF_ROUND(15) TF_ROUND(26) TF_ROUND(6)
    x0 += ks1; x1 += ks2 + 1u;
    TF_ROUND(17) TF_ROUND(29) TF_ROUND(16) TF_ROUND(24)
    x0 += ks2; x1 += ks0 + 2u;
    TF_ROUND(13) TF_ROUND(15) TF_ROUND(26) TF_ROUND(6)
    x0 += ks0; x1 += ks1 + 3u;
    TF_ROUND(17) TF_ROUND(29) TF_ROUND(16) TF_ROUND(24)
    x0 += ks1; x1 += ks2 + 4u;
    TF_ROUND(13) TF_ROUND(15) TF_ROUND(26) TF_ROUND(6)
    x0 += ks2; x1 += ks0 + 5u;
#undef TF_ROUND
    return ((x0 ^ x1) < KEEP_THRESH) ? 1u : 0u;
}

// ---------------------------------------------------------------------------
// split fp32 -> bf16 hi/lo for x1, x2
// ---------------------------------------------------------------------------
__global__ __launch_bounds__(256) void split_kernel(const float* __restrict__ x1,
                                                    const float* __restrict__ x2) {
    size_t i = (size_t)blockIdx.x * blockDim.x + threadIdx.x;
    float a = x1[i];
    __nv_bfloat16 h = __float2bfloat16(a);
    g_x1h[i] = h;
    g_x1l[i] = __float2bfloat16(a - __bfloat162float(h));
    float c = x2[i];
    __nv_bfloat16 h2 = __float2bfloat16(c);
    g_x2h[i] = h2;
    g_x2l[i] = __float2bfloat16(c - __bfloat162float(h2));
}

// ---------------------------------------------------------------------------
// Fused attention, 64-row q-tiles, 64-wide k-tiles, 4 warps / 128 threads.
// Threefry mask for tile t+1 is software-pipelined into tile t's PV-pass so
// its ALU chains fill the ldsm->mma stall shadows (in-order issue!).
// grid (q-tile=32, batch=16) = 512 CTAs.
// ---------------------------------------------------------------------------
__global__ __launch_bounds__(128, 2) void fused_attn(float* __restrict__ out) {
    extern __shared__ char smem[];
    uint32_t base = smem_u32(smem);
    const int tid = threadIdx.x;
    const int w = tid >> 5;
    const int lane = tid & 31;
    const int b = blockIdx.y;
    const int bq = blockIdx.x * 64;

    // x1 q-tile (hi/lo) resident for whole kernel
    const size_t aoff = ((size_t)b * NQ + bq) * DIM;
    load_tile64(base + SM_X1H, g_x1h + aoff, DIM);
    load_tile64(base + SM_X1L, g_x1l + aoff, DIM);

    const __nv_bfloat16* x2h = g_x2h + (size_t)b * NK * DIM;
    const __nv_bfloat16* x2l = g_x2l + (size_t)b * NK * DIM;
    // prefetch k-tile 0
    cp_tile64(base + SM_X2(0), x2h, DIM);
    cp_tile64(base + SM_X2(0) + 16384, x2l, DIM);
    CP_COMMIT();

    // fragment geometry
    const int arow = w * 16 + (lane & 15);
    const int acol = (lane >> 4) * 8;
    const int bro = ((lane >> 4) << 3) + (lane & 7);
    const int bco = ((lane >> 3) & 1) * 8;
    const int vro = ((lane >> 3) & 1) * 8 + (lane & 7);
    const int vco = (lane >> 4) * 8;
    const int qr = (lane & 3) * 2;  // col offset within n8 frag

    // softmax state + output accumulator
    float m0 = -INFINITY, m1 = -INFINITY, l0 = 0.0f, l1 = 0.0f;
    float O[16][4];
#pragma unroll
    for (int i = 0; i < 16; i++)
#pragma unroll
        for (int j = 0; j < 4; j++) O[i][j] = 0.0f;

    // dropout element-index bases: i = row_g * 2048 + col
    const unsigned row_g0 = (unsigned)(b * NQ + bq + w * 16 + (lane >> 2));
    const unsigned ib0 = row_g0 * 2048u + (unsigned)qr;
    const unsigned ib1 = ib0 + 8u * 2048u;

    // mask bits for tile 0 (pipeline prologue)
    unsigned km0 = 0u, km1 = 0u;
#pragma unroll
    for (int nf = 0; nf < 8; nf++) {
        km0 |= (tf_keep(ib0 + nf * 8) | (tf_keep(ib0 + nf * 8 + 1) << 1)) << (2 * nf);
        km1 |= (tf_keep(ib1 + nf * 8) | (tf_keep(ib1 + nf * 8 + 1) << 1)) << (2 * nf);
    }

    for (int t = 0; t < 32; t++) {
        if (t + 1 < 32) {
            cp_tile64(base + SM_X2((t + 1) & 1), x2h + (size_t)(t + 1) * 64 * DIM, DIM);
            cp_tile64(base + SM_X2((t + 1) & 1) + 16384, x2l + (size_t)(t + 1) * 64 * DIM, DIM);
            CP_COMMIT();
            asm volatile("cp.async.wait_group 1;" ::: "memory");
        } else {
            asm volatile("cp.async.wait_group 0;" ::: "memory");
        }
        __syncthreads();
        const uint32_t X2H = base + SM_X2(t & 1);
        const uint32_t X2L = X2H + 16384;

        // ---- S-pass: acc = x1 . x2^T (hi*hi + hi*lo + lo*hi), 16x64 ----
        float acc[8][4];
#pragma unroll
        for (int i = 0; i < 8; i++)
#pragma unroll
            for (int j = 0; j < 4; j++) acc[i][j] = 0.0f;

#pragma unroll
        for (int ks = 0; ks < 8; ks++) {
            uint32_t ah[4], al[4];
            ldsm_x4(ah, tile_addr(base + SM_X1H, arow, ks * 16 + acol));
            ldsm_x4(al, tile_addr(base + SM_X1L, arow, ks * 16 + acol));
#pragma unroll
            for (int nb = 0; nb < 4; nb++) {
                uint32_t bh[4], bl[4];
                ldsm_x4(bh, tile_addr(X2H, nb * 16 + bro, ks * 16 + bco));
                ldsm_x4(bl, tile_addr(X2L, nb * 16 + bro, ks * 16 + bco));
                mma16816(acc[2 * nb], ah, bh);
                mma16816(acc[2 * nb + 1], ah, bh + 2);
                mma16816(acc[2 * nb], ah, bl);
                mma16816(acc[2 * nb + 1], ah, bl + 2);
                mma16816(acc[2 * nb], al, bh);
                mma16816(acc[2 * nb + 1], al, bh + 2);
            }
        }

        // ---- online softmax: rescale state, exp, mask -> overwrite acc ----
        float tm0 = -INFINITY, tm1 = -INFINITY;
#pragma unroll
        for (int nf = 0; nf < 8; nf++) {
            acc[nf][0] *= SCALE; acc[nf][1] *= SCALE;
            acc[nf][2] *= SCALE; acc[nf][3] *= SCALE;
            tm0 = fmaxf(tm0, fmaxf(acc[nf][0], acc[nf][1]));
            tm1 = fmaxf(tm1, fmaxf(acc[nf][2], acc[nf][3]));
        }
        tm0 = fmaxf(tm0, __shfl_xor_sync(0xffffffffu, tm0, 1));
        tm0 = fmaxf(tm0, __shfl_xor_sync(0xffffffffu, tm0, 2));
        tm1 = fmaxf(tm1, __shfl_xor_sync(0xffffffffu, tm1, 1));
        tm1 = fmaxf(tm1, __shfl_xor_sync(0xffffffffu, tm1, 2));
        const float nm0 = fmaxf(m0, tm0);
        const float nm1 = fmaxf(m1, tm1);
        const float f0 = __expf(m0 - nm0);
        const float f1 = __expf(m1 - nm1);
        m0 = nm0; m1 = nm1;
        l0 *= f0; l1 *= f1;
#pragma unroll
        for (int nf = 0; nf < 16; nf++) {
            O[nf][0] *= f0; O[nf][1] *= f0;
            O[nf][2] *= f1; O[nf][3] *= f1;
        }

#pragma unroll
        for (int nf = 0; nf < 8; nf++) {
            float e0 = __expf(acc[nf][0] - m0);
            float e1 = __expf(acc[nf][1] - m0);
            float e2 = __expf(acc[nf][2] - m1);
            float e3 = __expf(acc[nf][3] - m1);
            l0 += e0 + e1;
            l1 += e2 + e3;
            unsigned w0 = km0 >> (2 * nf);
            unsigned w1 = km1 >> (2 * nf);
            acc[nf][0] = (w0 & 1u) ? e0 : 0.0f;
            acc[nf][1] = (w0 & 2u) ? e1 : 0.0f;
            acc[nf][2] = (w1 & 1u) ? e2 : 0.0f;
            acc[nf][3] = (w1 & 2u) ? e3 : 0.0f;
        }

        // ---- PV-pass with next-tile threefry interleaved into the stall
        //      shadows (8 evals per ks step = 32 total for tile t+1) ----
        const unsigned ne0 = ib0 + (unsigned)(t + 1) * 64u;
        const unsigned ne1 = ib1 + (unsigned)(t + 1) * 64u;
        unsigned nkm0 = 0u, nkm1 = 0u;
#pragma unroll
        for (int ks = 0; ks < 4; ks++) {
            uint32_t ah[4], al[4];
#pragma unroll
            for (int h = 0; h < 2; h++) {
                const float* a4 = acc[2 * ks + h];
                uint32_t h0 = pack_bf16(a4[0], a4[1]);
                uint32_t h1 = pack_bf16(a4[2], a4[3]);
                ah[2 * h + 0] = h0;
                ah[2 * h + 1] = h1;
                al[2 * h + 0] = pack_bf16(a4[0] - __uint_as_float(h0 << 16),
                                          a4[1] - __uint_as_float(h0 & 0xffff0000u));
                al[2 * h + 1] = pack_bf16(a4[2] - __uint_as_float(h1 << 16),
                                          a4[3] - __uint_as_float(h1 & 0xffff0000u));
            }
            // next-tile mask, fragments 2ks and 2ks+1 (independent ALU chains;
            // compiler schedules them into the ldsm/mma shadows below)
            {
                const int nfa = 2 * ks, nfb = 2 * ks + 1;
                nkm0 |= (tf_keep(ne0 + nfa * 8) | (tf_keep(ne0 + nfa * 8 + 1) << 1)) << (2 * nfa);
                nkm0 |= (tf_keep(ne0 + nfb * 8) | (tf_keep(ne0 + nfb * 8 + 1) << 1)) << (2 * nfb);
                nkm1 |= (tf_keep(ne1 + nfa * 8) | (tf_keep(ne1 + nfa * 8 + 1) << 1)) << (2 * nfa);
                nkm1 |= (tf_keep(ne1 + nfb * 8) | (tf_keep(ne1 + nfb * 8 + 1) << 1)) << (2 * nfb);
            }
#pragma unroll
            for (int nb = 0; nb < 8; nb++) {
                uint32_t vh[4], vl[4];
                ldsm_x4_t(vh, tile_addr(X2H, ks * 16 + vro, nb * 16 + vco));
                ldsm_x4_t(vl, tile_addr(X2L, ks * 16 + vro, nb * 16 + vco));
                mma16816(O[2 * nb], ah, vh);
                mma16816(O[2 * nb + 1], ah, vh + 2);
                mma16816(O[2 * nb], ah, vl);
                mma16816(O[2 * nb + 1], ah, vl + 2);
                mma16816(O[2 * nb], al, vh);
                mma16816(O[2 * nb + 1], al, vh + 2);
            }
        }
        km0 = nkm0;
        km1 = nkm1;
        __syncthreads();  // all warps done with this x2 buffer before next prefetch reuses it
    }

    // ---- epilogue: O / (l * 0.7) ----
    l0 += __shfl_xor_sync(0xffffffffu, l0, 1);
    l0 += __shfl_xor_sync(0xffffffffu, l0, 2);
    l1 += __shfl_xor_sync(0xffffffffu, l1, 1);
    l1 += __shfl_xor_sync(0xffffffffu, l1, 2);
    const float s0 = INV_KEEP / l0;
    const float s1 = INV_KEEP / l1;

    const int rg = bq + w * 16 + (lane >> 2);
    float* C = out + ((size_t)b * NQ + rg) * DIM;
#pragma unroll
    for (int nf = 0; nf < 16; nf++) {
        const int c0 = nf * 8 + qr;
        *(float2*)(C + c0) = make_float2(O[nf][0] * s0, O[nf][1] * s0);
        *(float2*)(C + 8 * DIM + c0) = make_float2(O[nf][2] * s1, O[nf][3] * s1);
    }
}

// ---------------------------------------------------------------------------
extern "C" void kernel_launch(void* const* d_in, const int* in_sizes, int n_in,
                              void* d_out, int out_size) {
    const float* x1 = (const float*)d_in[0];
    const float* x2 = (const float*)d_in[1];
    float* out = (float*)d_out;

    cudaFuncSetAttribute(fused_attn, cudaFuncAttributeMaxDynamicSharedMemorySize, SMEM_BYTES);

    split_kernel<<<(BATCH * NQ * DIM) / 256, 256>>>(x1, x2);
    fused_attn<<<dim3(32, 16), 128, SMEM_BYTES>>>(out);
}

// round 16
// speedup vs baseline: 1.0302x; 1.0302x over previous
#include <cuda_runtime.h>
#include <cuda_bf16.h>
#include <cstdint>

#define BATCH 16
#define NQ 2048
#define NK 2048
#define DIM 128
#define SCALE 1.153f
#define INV_KEEP (1.0f / 0.7f)
#define KEEP_THRESH 0xB3333400u

// ---------------- scratch ---------------------------------------------------
static __device__ __nv_bfloat16 g_x1h[(size_t)BATCH * NQ * DIM];
static __device__ __nv_bfloat16 g_x1l[(size_t)BATCH * NQ * DIM];
static __device__ __nv_bfloat16 g_x2h[(size_t)BATCH * NK * DIM];
static __device__ __nv_bfloat16 g_x2l[(size_t)BATCH * NK * DIM];

// ---------------- helpers ---------------------------------------------------
__device__ __forceinline__ uint32_t smem_u32(const void* p) {
    uint32_t a;
    asm("{ .reg .u64 t; cvta.to.shared.u64 t, %1; cvt.u32.u64 %0, t; }" : "=r"(a) : "l"(p));
    return a;
}
__device__ __forceinline__ void mma16816(float* d, const uint32_t* a, const uint32_t* b) {
    asm volatile(
        "mma.sync.aligned.m16n8k16.row.col.f32.bf16.bf16.f32 "
        "{%0,%1,%2,%3}, {%4,%5,%6,%7}, {%8,%9}, {%0,%1,%2,%3};"
        : "+f"(d[0]), "+f"(d[1]), "+f"(d[2]), "+f"(d[3])
        : "r"(a[0]), "r"(a[1]), "r"(a[2]), "r"(a[3]), "r"(b[0]), "r"(b[1]));
}
__device__ __forceinline__ void ldsm_x4(uint32_t* r, uint32_t addr) {
    asm volatile("ldmatrix.sync.aligned.m8n8.x4.shared.b16 {%0,%1,%2,%3}, [%4];"
                 : "=r"(r[0]), "=r"(r[1]), "=r"(r[2]), "=r"(r[3]) : "r"(addr));
}
__device__ __forceinline__ void ldsm_x4_t(uint32_t* r, uint32_t addr) {
    asm volatile("ldmatrix.sync.aligned.m8n8.x4.trans.shared.b16 {%0,%1,%2,%3}, [%4];"
                 : "=r"(r[0]), "=r"(r[1]), "=r"(r[2]), "=r"(r[3]) : "r"(addr));
}
__device__ __forceinline__ uint32_t pack_bf16(float lo, float hi) {
    uint32_t r;
    asm("cvt.rn.bf16x2.f32 %0, %1, %2;" : "=r"(r) : "f"(hi), "f"(lo));
    return r;
}
__device__ __forceinline__ void cp_async16(uint32_t dst, const void* src) {
    asm volatile("cp.async.cg.shared.global [%0], [%1], 16;" :: "r"(dst), "l"(src));
}
#define CP_COMMIT() asm volatile("cp.async.commit_group;" ::: "memory")

// bf16 tile with 256B/row (128 cols), XOR swizzle on 16B granules
__device__ __forceinline__ uint32_t tile_addr(uint32_t base, int row, int col) {
    return base + row * 256 + ((((col >> 3) ^ (row & 7)) << 4));
}
// 64-row tile sync load (x1, 128 threads): 1024 granules, 8 per thread
__device__ __forceinline__ void load_tile64(uint32_t dst, const __nv_bfloat16* __restrict__ src,
                                            int ld) {
    const int tid = threadIdx.x;
#pragma unroll
    for (int i = 0; i < 8; i++) {
        int idx = tid + i * 128;
        int row = idx >> 4, g = idx & 15;
        uint4 v = *(const uint4*)(src + (size_t)row * ld + g * 8);
        uint32_t a = dst + row * 256 + ((g ^ (row & 7)) << 4);
        asm volatile("st.shared.v4.b32 [%0], {%1,%2,%3,%4};"
                     :: "r"(a), "r"(v.x), "r"(v.y), "r"(v.z), "r"(v.w));
    }
}
// 64-row tile async copy (x2 k-tile, 128 threads): 1024 granules, 8 per thread
__device__ __forceinline__ void cp_tile64(uint32_t dst, const __nv_bfloat16* __restrict__ src,
                                          int ld) {
    const int tid = threadIdx.x;
#pragma unroll
    for (int i = 0; i < 8; i++) {
        int idx = tid + i * 128;
        int row = idx >> 4, g = idx & 15;
        cp_async16(dst + row * 256 + ((g ^ (row & 7)) << 4), src + (size_t)row * ld + g * 8);
    }
}

#define SM_X1H 0
#define SM_X1L 16384
// each X2 buffer: hi tile (16KB) + lo tile (16KB)
#define SM_X2(buf) (32768 + (buf) * 32768)
#define SMEM_BYTES (32768 + 2 * 32768)  // 96KB -> 2 CTAs/SM

// ---------------------------------------------------------------------------
// threefry2x32, jax partitionable semantics (verified exact)
// ---------------------------------------------------------------------------
__device__ __forceinline__ unsigned rotl32(unsigned x, int r) { return __funnelshift_l(x, x, r); }

__device__ __forceinline__ unsigned tf_keep(unsigned i) {
    const unsigned ks0 = 0u, ks1 = 42u, ks2 = 0x1BD11BDAu ^ ks0 ^ ks1;
    unsigned x0 = ks0, x1 = i + ks1;
#define TF_ROUND(r) { x0 += x1; x1 = rotl32(x1, (r)); x1 ^= x0; }
    TF_ROUND(13) TF_ROUND(15) TF_ROUND(26) TF_ROUND(6)
    x0 += ks1; x1 += ks2 + 1u;
    TF_ROUND(17) TF_ROUND(29) TF_ROUND(16) TF_ROUND(24)
    x0 += ks2; x1 += ks0 + 2u;
    TF_ROUND(13) TF_ROUND(15) TF_ROUND(26) TF_ROUND(6)
    x0 += ks0; x1 += ks1 + 3u;
    TF_ROUND(17) TF_ROUND(29) TF_ROUND(16) TF_ROUND(24)
    x0 += ks1; x1 += ks2 + 4u;
    TF_ROUND(13) TF_ROUND(15) TF_ROUND(26) TF_ROUND(6)
    x0 += ks2; x1 += ks0 + 5u;
#undef TF_ROUND
    return ((x0 ^ x1) < KEEP_THRESH) ? 1u : 0u;
}

// ---------------------------------------------------------------------------
// split fp32 -> bf16 hi/lo for x1, x2
// ---------------------------------------------------------------------------
__global__ __launch_bounds__(256) void split_kernel(const float* __restrict__ x1,
                                                    const float* __restrict__ x2) {
    size_t i = (size_t)blockIdx.x * blockDim.x + threadIdx.x;
    float a = x1[i];
    __nv_bfloat16 h = __float2bfloat16(a);
    g_x1h[i] = h;
    g_x1l[i] = __float2bfloat16(a - __bfloat162float(h));
    float c = x2[i];
    __nv_bfloat16 h2 = __float2bfloat16(c);
    g_x2h[i] = h2;
    g_x2l[i] = __float2bfloat16(c - __bfloat162float(h2));
}

// ---------------------------------------------------------------------------
// Fused attention, 64-row q-tiles, 64-wide k-tiles, 4 warps / 128 threads.
// Fragment double-buffering: every ldsm is issued one nb-step ahead of its
// consuming mma so the ~30cyc ldsm latency drains under the tensor pipe.
// grid (q-tile=32, batch=16) = 512 CTAs, 2 CTAs/SM.
// ---------------------------------------------------------------------------
__global__ __launch_bounds__(128, 2) void fused_attn(float* __restrict__ out) {
    extern __shared__ char smem[];
    uint32_t base = smem_u32(smem);
    const int tid = threadIdx.x;
    const int w = tid >> 5;
    const int lane = tid & 31;
    const int b = blockIdx.y;
    const int bq = blockIdx.x * 64;

    // x1 q-tile (hi/lo) resident for whole kernel
    const size_t aoff = ((size_t)b * NQ + bq) * DIM;
    load_tile64(base + SM_X1H, g_x1h + aoff, DIM);
    load_tile64(base + SM_X1L, g_x1l + aoff, DIM);

    const __nv_bfloat16* x2h = g_x2h + (size_t)b * NK * DIM;
    const __nv_bfloat16* x2l = g_x2l + (size_t)b * NK * DIM;
    // prefetch k-tile 0
    cp_tile64(base + SM_X2(0), x2h, DIM);
    cp_tile64(base + SM_X2(0) + 16384, x2l, DIM);
    CP_COMMIT();

    // fragment geometry
    const int arow = w * 16 + (lane & 15);
    const int acol = (lane >> 4) * 8;
    const int bro = ((lane >> 4) << 3) + (lane & 7);
    const int bco = ((lane >> 3) & 1) * 8;
    const int vro = ((lane >> 3) & 1) * 8 + (lane & 7);
    const int vco = (lane >> 4) * 8;
    const int qr = (lane & 3) * 2;  // col offset within n8 frag

    // softmax state + output accumulator
    float m0 = -INFINITY, m1 = -INFINITY, l0 = 0.0f, l1 = 0.0f;
    float O[16][4];
#pragma unroll
    for (int i = 0; i < 16; i++)
#pragma unroll
        for (int j = 0; j < 4; j++) O[i][j] = 0.0f;

    // dropout element-index bases: i = row_g * 2048 + col
    const unsigned row_g0 = (unsigned)(b * NQ + bq + w * 16 + (lane >> 2));
    const unsigned ib0 = row_g0 * 2048u + (unsigned)qr;
    const unsigned ib1 = ib0 + 8u * 2048u;

    for (int t = 0; t < 32; t++) {
        if (t + 1 < 32) {
            cp_tile64(base + SM_X2((t + 1) & 1), x2h + (size_t)(t + 1) * 64 * DIM, DIM);
            cp_tile64(base + SM_X2((t + 1) & 1) + 16384, x2l + (size_t)(t + 1) * 64 * DIM, DIM);
            CP_COMMIT();
            asm volatile("cp.async.wait_group 1;" ::: "memory");
        } else {
            asm volatile("cp.async.wait_group 0;" ::: "memory");
        }
        __syncthreads();
        const uint32_t X2H = base + SM_X2(t & 1);
        const uint32_t X2L = X2H + 16384;

        // ---- inline dropout mask bits for this k-tile (32 evals) ----
        unsigned km0 = 0u, km1 = 0u;
        {
            const unsigned e0 = ib0 + (unsigned)t * 64u;
            const unsigned e1 = ib1 + (unsigned)t * 64u;
#pragma unroll
            for (int nf = 0; nf < 8; nf++) {
                km0 |= (tf_keep(e0 + nf * 8) | (tf_keep(e0 + nf * 8 + 1) << 1)) << (2 * nf);
                km1 |= (tf_keep(e1 + nf * 8) | (tf_keep(e1 + nf * 8 + 1) << 1)) << (2 * nf);
            }
        }

        // ---- S-pass: acc = x1 . x2^T (hi*hi + hi*lo + lo*hi), 16x64 ----
        // Fragment-pipelined: B frags double-buffered across nb; A frags
        // prefetched one ks ahead.
        float acc[8][4];
#pragma unroll
        for (int i = 0; i < 8; i++)
#pragma unroll
            for (int j = 0; j < 4; j++) acc[i][j] = 0.0f;

        {
            uint32_t ah[4], al[4], ahn[4], aln[4], bh[2][4], bl[2][4];
            ldsm_x4(ah, tile_addr(base + SM_X1H, arow, acol));
            ldsm_x4(al, tile_addr(base + SM_X1L, arow, acol));
            ldsm_x4(bh[0], tile_addr(X2H, bro, bco));
            ldsm_x4(bl[0], tile_addr(X2L, bro, bco));
#pragma unroll
            for (int ks = 0; ks < 8; ks++) {
#pragma unroll
                for (int nb = 0; nb < 4; nb++) {
                    const int cur = nb & 1, nxt = cur ^ 1;
                    if (nb < 3) {
                        ldsm_x4(bh[nxt], tile_addr(X2H, (nb + 1) * 16 + bro, ks * 16 + bco));
                        ldsm_x4(bl[nxt], tile_addr(X2L, (nb + 1) * 16 + bro, ks * 16 + bco));
                    } else if (ks < 7) {
                        ldsm_x4(bh[nxt], tile_addr(X2H, bro, (ks + 1) * 16 + bco));
                        ldsm_x4(bl[nxt], tile_addr(X2L, bro, (ks + 1) * 16 + bco));
                        ldsm_x4(ahn, tile_addr(base + SM_X1H, arow, (ks + 1) * 16 + acol));
                        ldsm_x4(aln, tile_addr(base + SM_X1L, arow, (ks + 1) * 16 + acol));
                    }
                    mma16816(acc[2 * nb], ah, bh[cur]);
                    mma16816(acc[2 * nb + 1], ah, bh[cur] + 2);
                    mma16816(acc[2 * nb], ah, bl[cur]);
                    mma16816(acc[2 * nb + 1], ah, bl[cur] + 2);
                    mma16816(acc[2 * nb], al, bh[cur]);
                    mma16816(acc[2 * nb + 1], al, bh[cur] + 2);
                }
                if (ks < 7) {
#pragma unroll
                    for (int i = 0; i < 4; i++) { ah[i] = ahn[i]; al[i] = aln[i]; }
                }
            }
        }

        // ---- online softmax: rescale state, exp, mask -> overwrite acc ----
        float tm0 = -INFINITY, tm1 = -INFINITY;
#pragma unroll
        for (int nf = 0; nf < 8; nf++) {
            acc[nf][0] *= SCALE; acc[nf][1] *= SCALE;
            acc[nf][2] *= SCALE; acc[nf][3] *= SCALE;
            tm0 = fmaxf(tm0, fmaxf(acc[nf][0], acc[nf][1]));
            tm1 = fmaxf(tm1, fmaxf(acc[nf][2], acc[nf][3]));
        }
        tm0 = fmaxf(tm0, __shfl_xor_sync(0xffffffffu, tm0, 1));
        tm0 = fmaxf(tm0, __shfl_xor_sync(0xffffffffu, tm0, 2));
        tm1 = fmaxf(tm1, __shfl_xor_sync(0xffffffffu, tm1, 1));
        tm1 = fmaxf(tm1, __shfl_xor_sync(0xffffffffu, tm1, 2));
        const float nm0 = fmaxf(m0, tm0);
        const float nm1 = fmaxf(m1, tm1);
        const float f0 = __expf(m0 - nm0);
        const float f1 = __expf(m1 - nm1);
        m0 = nm0; m1 = nm1;
        l0 *= f0; l1 *= f1;
#pragma unroll
        for (int nf = 0; nf < 16; nf++) {
            O[nf][0] *= f0; O[nf][1] *= f0;
            O[nf][2] *= f1; O[nf][3] *= f1;
        }

#pragma unroll
        for (int nf = 0; nf < 8; nf++) {
            float e0 = __expf(acc[nf][0] - m0);
            float e1 = __expf(acc[nf][1] - m0);
            float e2 = __expf(acc[nf][2] - m1);
            float e3 = __expf(acc[nf][3] - m1);
            l0 += e0 + e1;
            l1 += e2 + e3;
            unsigned w0 = km0 >> (2 * nf);
            unsigned w1 = km1 >> (2 * nf);
            acc[nf][0] = (w0 & 1u) ? e0 : 0.0f;
            acc[nf][1] = (w0 & 2u) ? e1 : 0.0f;
            acc[nf][2] = (w1 & 1u) ? e2 : 0.0f;
            acc[nf][3] = (w1 & 2u) ? e3 : 0.0f;
        }

        // ---- PV-pass: pack P on the fly, O += P . V; V frags pipelined ----
        {
            uint32_t vh[2][4], vl[2][4];
            ldsm_x4_t(vh[0], tile_addr(X2H, vro, vco));
            ldsm_x4_t(vl[0], tile_addr(X2L, vro, vco));
#pragma unroll
            for (int ks = 0; ks < 4; ks++) {
                uint32_t ph[4], pl[4];
#pragma unroll
                for (int h = 0; h < 2; h++) {
                    const float* a4 = acc[2 * ks + h];
                    uint32_t h0 = pack_bf16(a4[0], a4[1]);
                    uint32_t h1 = pack_bf16(a4[2], a4[3]);
                    ph[2 * h + 0] = h0;
                    ph[2 * h + 1] = h1;
                    pl[2 * h + 0] = pack_bf16(a4[0] - __uint_as_float(h0 << 16),
                                              a4[1] - __uint_as_float(h0 & 0xffff0000u));
                    pl[2 * h + 1] = pack_bf16(a4[2] - __uint_as_float(h1 << 16),
                                              a4[3] - __uint_as_float(h1 & 0xffff0000u));
                }
#pragma unroll
                for (int nb = 0; nb < 8; nb++) {
                    const int cur = nb & 1, nxt = cur ^ 1;
                    if (nb < 7) {
                        ldsm_x4_t(vh[nxt], tile_addr(X2H, ks * 16 + vro, (nb + 1) * 16 + vco));
                        ldsm_x4_t(vl[nxt], tile_addr(X2L, ks * 16 + vro, (nb + 1) * 16 + vco));
                    } else if (ks < 3) {
                        ldsm_x4_t(vh[nxt], tile_addr(X2H, (ks + 1) * 16 + vro, vco));
                        ldsm_x4_t(vl[nxt], tile_addr(X2L, (ks + 1) * 16 + vro, vco));
                    }
                    mma16816(O[2 * nb], ph, vh[cur]);
                    mma16816(O[2 * nb + 1], ph, vh[cur] + 2);
                    mma16816(O[2 * nb], ph, vl[cur]);
                    mma16816(O[2 * nb + 1], ph, vl[cur] + 2);
                    mma16816(O[2 * nb], pl, vh[cur]);
                    mma16816(O[2 * nb + 1], pl, vh[cur] + 2);
                }
            }
        }
        __syncthreads();  // all warps done with this x2 buffer before next prefetch reuses it
    }

    // ---- epilogue: O / (l * 0.7) ----
    l0 += __shfl_xor_sync(0xffffffffu, l0, 1);
    l0 += __shfl_xor_sync(0xffffffffu, l0, 2);
    l1 += __shfl_xor_sync(0xffffffffu, l1, 1);
    l1 += __shfl_xor_sync(0xffffffffu, l1, 2);
    const float s0 = INV_KEEP / l0;
    const float s1 = INV_KEEP / l1;

    const int rg = bq + w * 16 + (lane >> 2);
    float* C = out + ((size_t)b * NQ + rg) * DIM;
#pragma unroll
    for (int nf = 0; nf < 16; nf++) {
        const int c0 = nf * 8 + qr;
        *(float2*)(C + c0) = make_float2(O[nf][0] * s0, O[nf][1] * s0);
        *(float2*)(C + 8 * DIM + c0) = make_float2(O[nf][2] * s1, O[nf][3] * s1);
    }
}

// ---------------------------------------------------------------------------
extern "C" void kernel_launch(void* const* d_in, const int* in_sizes, int n_in,
                              void* d_out, int out_size) {
    const float* x1 = (const float*)d_in[0];
    const float* x2 = (const float*)d_in[1];
    float* out = (float*)d_out;

    cudaFuncSetAttribute(fused_attn, cudaFuncAttributeMaxDynamicSharedMemorySize, SMEM_BYTES);

    split_kernel<<<(BATCH * NQ * DIM) / 256, 256>>>(x1, x2);
    fused_attn<<<dim3(32, 16), 128, SMEM_BYTES>>>(out);
}

// round 17
// speedup vs baseline: 1.1262x; 1.0931x over previous
#include <cuda_runtime.h>
#include <cuda_bf16.h>
#include <cstdint>

#define BATCH 16
#define NQ 2048
#define NK 2048
#define DIM 128
#define SCALE 1.153f
#define INV_KEEP (1.0f / 0.7f)
#define KEEP_THRESH 0xB3333400u

// ---------------- scratch ---------------------------------------------------
static __device__ __nv_bfloat16 g_x1h[(size_t)BATCH * NQ * DIM];
static __device__ __nv_bfloat16 g_x1l[(size_t)BATCH * NQ * DIM];
static __device__ __nv_bfloat16 g_x2h[(size_t)BATCH * NK * DIM];
static __device__ __nv_bfloat16 g_x2l[(size_t)BATCH * NK * DIM];

// ---------------- helpers ---------------------------------------------------
__device__ __forceinline__ uint32_t smem_u32(const void* p) {
    uint32_t a;
    asm("{ .reg .u64 t; cvta.to.shared.u64 t, %1; cvt.u32.u64 %0, t; }" : "=r"(a) : "l"(p));
    return a;
}
__device__ __forceinline__ void mma16816(float* d, const uint32_t* a, const uint32_t* b) {
    asm volatile(
        "mma.sync.aligned.m16n8k16.row.col.f32.bf16.bf16.f32 "
        "{%0,%1,%2,%3}, {%4,%5,%6,%7}, {%8,%9}, {%0,%1,%2,%3};"
        : "+f"(d[0]), "+f"(d[1]), "+f"(d[2]), "+f"(d[3])
        : "r"(a[0]), "r"(a[1]), "r"(a[2]), "r"(a[3]), "r"(b[0]), "r"(b[1]));
}
__device__ __forceinline__ void ldsm_x4(uint32_t* r, uint32_t addr) {
    asm volatile("ldmatrix.sync.aligned.m8n8.x4.shared.b16 {%0,%1,%2,%3}, [%4];"
                 : "=r"(r[0]), "=r"(r[1]), "=r"(r[2]), "=r"(r[3]) : "r"(addr));
}
__device__ __forceinline__ void ldsm_x4_t(uint32_t* r, uint32_t addr) {
    asm volatile("ldmatrix.sync.aligned.m8n8.x4.trans.shared.b16 {%0,%1,%2,%3}, [%4];"
                 : "=r"(r[0]), "=r"(r[1]), "=r"(r[2]), "=r"(r[3]) : "r"(addr));
}
__device__ __forceinline__ uint32_t pack_bf16(float lo, float hi) {
    uint32_t r;
    asm("cvt.rn.bf16x2.f32 %0, %1, %2;" : "=r"(r) : "f"(hi), "f"(lo));
    return r;
}
__device__ __forceinline__ void cp_async16(uint32_t dst, const void* src) {
    asm volatile("cp.async.cg.shared.global [%0], [%1], 16;" :: "r"(dst), "l"(src));
}
#define CP_COMMIT() asm volatile("cp.async.commit_group;" ::: "memory")
#define BAR_CONS()  asm volatile("bar.sync 1, 128;" ::: "memory")
#define BAR_PROD()  asm volatile("bar.sync 2, 128;" ::: "memory")

// bf16 tile with 256B/row (128 cols), XOR swizzle on 16B granules
__device__ __forceinline__ uint32_t tile_addr(uint32_t base, int row, int col) {
    return base + row * 256 + ((((col >> 3) ^ (row & 7)) << 4));
}
// 64-row tile sync load (x1, 128 consumer threads)
__device__ __forceinline__ void load_tile64(uint32_t dst, const __nv_bfloat16* __restrict__ src,
                                            int ld) {
    const int tid = threadIdx.x;  // 0..127 (consumer path only)
#pragma unroll
    for (int i = 0; i < 8; i++) {
        int idx = tid + i * 128;
        int row = idx >> 4, g = idx & 15;
        uint4 v = *(const uint4*)(src + (size_t)row * ld + g * 8);
        uint32_t a = dst + row * 256 + ((g ^ (row & 7)) << 4);
        asm volatile("st.shared.v4.b32 [%0], {%1,%2,%3,%4};"
                     :: "r"(a), "r"(v.x), "r"(v.y), "r"(v.z), "r"(v.w));
    }
}
// 64-row tile async copy (x2 k-tile, 128 consumer threads)
__device__ __forceinline__ void cp_tile64(uint32_t dst, const __nv_bfloat16* __restrict__ src,
                                          int ld) {
    const int tid = threadIdx.x;
#pragma unroll
    for (int i = 0; i < 8; i++) {
        int idx = tid + i * 128;
        int row = idx >> 4, g = idx & 15;
        cp_async16(dst + row * 256 + ((g ^ (row & 7)) << 4), src + (size_t)row * ld + g * 8);
    }
}

#define SM_X1H 0
#define SM_X1L 16384
#define SM_X2(buf) (32768 + (buf) * 32768)  // hi at +0, lo at +16384
#define OFF_RING 98304                       // ring[2][64][2] uint32 = 1KB
#define OFF_PC   (OFF_RING + 1024)           // produced-tiles counter (int)
#define OFF_CC   (OFF_PC + 4)                // consumed-tiles counter (int)
#define SMEM_BYTES (OFF_CC + 4 + 120)        // ~99.5KB -> 1 CTA/SM

// ---------------------------------------------------------------------------
// threefry2x32, jax partitionable semantics (verified exact)
// ---------------------------------------------------------------------------
__device__ __forceinline__ unsigned rotl32(unsigned x, int r) { return __funnelshift_l(x, x, r); }

__device__ __forceinline__ unsigned tf_keep(unsigned i) {
    const unsigned ks0 = 0u, ks1 = 42u, ks2 = 0x1BD11BDAu ^ ks0 ^ ks1;
    unsigned x0 = ks0, x1 = i + ks1;
#define TF_ROUND(r) { x0 += x1; x1 = rotl32(x1, (r)); x1 ^= x0; }
    TF_ROUND(13) TF_ROUND(15) TF_ROUND(26) TF_ROUND(6)
    x0 += ks1; x1 += ks2 + 1u;
    TF_ROUND(17) TF_ROUND(29) TF_ROUND(16) TF_ROUND(24)
    x0 += ks2; x1 += ks0 + 2u;
    TF_ROUND(13) TF_ROUND(15) TF_ROUND(26) TF_ROUND(6)
    x0 += ks0; x1 += ks1 + 3u;
    TF_ROUND(17) TF_ROUND(29) TF_ROUND(16) TF_ROUND(24)
    x0 += ks1; x1 += ks2 + 4u;
    TF_ROUND(13) TF_ROUND(15) TF_ROUND(26) TF_ROUND(6)
    x0 += ks2; x1 += ks0 + 5u;
#undef TF_ROUND
    return ((x0 ^ x1) < KEEP_THRESH) ? 1u : 0u;
}

// ---------------------------------------------------------------------------
// split fp32 -> bf16 hi/lo for x1, x2
// ---------------------------------------------------------------------------
__global__ __launch_bounds__(256) void split_kernel(const float* __restrict__ x1,
                                                    const float* __restrict__ x2) {
    size_t i = (size_t)blockIdx.x * blockDim.x + threadIdx.x;
    float a = x1[i];
    __nv_bfloat16 h = __float2bfloat16(a);
    g_x1h[i] = h;
    g_x1l[i] = __float2bfloat16(a - __bfloat162float(h));
    float c = x2[i];
    __nv_bfloat16 h2 = __float2bfloat16(c);
    g_x2h[i] = h2;
    g_x2l[i] = __float2bfloat16(c - __bfloat162float(h2));
}

// ---------------------------------------------------------------------------
// Warp-specialized fused attention.
// Warps 0-3 (tid<128): S = x1 x2^T, online softmax, dropout, O += P V.
// Warps 4-7: threefry mask producers -> smem ring, 2 tiles deep.
// grid (q-tile=32, batch=16) = 512 CTAs, 256 threads, 1 CTA/SM.
// ---------------------------------------------------------------------------
__global__ __launch_bounds__(256, 1) void fused_attn(float* __restrict__ out) {
    extern __shared__ char smem[];
    uint32_t base = smem_u32(smem);
    const int tid = threadIdx.x;
    const int lane = tid & 31;
    const int b = blockIdx.y;
    const int bq = blockIdx.x * 64;

    volatile int* pc = (volatile int*)(smem + OFF_PC);
    volatile int* cc = (volatile int*)(smem + OFF_CC);
    if (tid == 0) { *pc = 0; *cc = 0; }
    __syncthreads();  // the ONLY all-thread barrier

    // =================== PRODUCER warps (tid >= 128) =======================
    if (tid >= 128) {
        const int p = (tid >> 5) - 4;          // 0..3
        const int prow = p * 16 + (lane >> 1); // local row 0..63
        const int pword = lane & 1;            // word 0 or 1 (32 cols each)
        const unsigned rowg = (unsigned)(b * NQ + bq + prow);
        uint32_t* ring = (uint32_t*)(smem + OFF_RING);

        for (int t = 0; t < 32; t++) {
            while (*cc < t - 1) __nanosleep(64);  // slot (t&1) free?
            unsigned word = 0u;
            const unsigned ebase = rowg * 2048u + (unsigned)t * 64u + (unsigned)pword * 32u;
#pragma unroll 8
            for (int bit = 0; bit < 32; bit++)
                word |= tf_keep(ebase + bit) << bit;
            ring[((t & 1) * 64 + prow) * 2 + pword] = word;
            BAR_PROD();                           // all producer writes done (drains STS)
            if (tid == 128) *pc = t + 1;
        }
        return;
    }

    // =================== CONSUMER warps (tid < 128) ========================
    const int w = tid >> 5;  // 0..3

    // x1 q-tile (hi/lo) resident for whole kernel
    const size_t aoff = ((size_t)b * NQ + bq) * DIM;
    load_tile64(base + SM_X1H, g_x1h + aoff, DIM);
    load_tile64(base + SM_X1L, g_x1l + aoff, DIM);

    const __nv_bfloat16* x2h = g_x2h + (size_t)b * NK * DIM;
    const __nv_bfloat16* x2l = g_x2l + (size_t)b * NK * DIM;
    // prefetch k-tile 0
    cp_tile64(base + SM_X2(0), x2h, DIM);
    cp_tile64(base + SM_X2(0) + 16384, x2l, DIM);
    CP_COMMIT();

    // fragment geometry
    const int arow = w * 16 + (lane & 15);
    const int acol = (lane >> 4) * 8;
    const int bro = ((lane >> 4) << 3) + (lane & 7);
    const int bco = ((lane >> 3) & 1) * 8;
    const int vro = ((lane >> 3) & 1) * 8 + (lane & 7);
    const int vco = (lane >> 4) * 8;
    const int qr = (lane & 3) * 2;  // col offset within n8 frag

    // mask ring addresses for this thread's two rows
    const int r0 = w * 16 + (lane >> 2);
    const int r1 = r0 + 8;
    const uint32_t* ring = (const uint32_t*)(smem + OFF_RING);

    // softmax state + output accumulator
    float m0 = -INFINITY, m1 = -INFINITY, l0 = 0.0f, l1 = 0.0f;
    float O[16][4];
#pragma unroll
    for (int i = 0; i < 16; i++)
#pragma unroll
        for (int j = 0; j < 4; j++) O[i][j] = 0.0f;

    for (int t = 0; t < 32; t++) {
        if (t + 1 < 32) {
            cp_tile64(base + SM_X2((t + 1) & 1), x2h + (size_t)(t + 1) * 64 * DIM, DIM);
            cp_tile64(base + SM_X2((t + 1) & 1) + 16384, x2l + (size_t)(t + 1) * 64 * DIM, DIM);
            CP_COMMIT();
            asm volatile("cp.async.wait_group 1;" ::: "memory");
        } else {
            asm volatile("cp.async.wait_group 0;" ::: "memory");
        }
        BAR_CONS();
        const uint32_t X2H = base + SM_X2(t & 1);
        const uint32_t X2L = X2H + 16384;

        // ---- wait for this tile's mask and read it (early) ----
        while (*pc < t + 1) __nanosleep(32);
        __threadfence_block();
        const int sbase = ((t & 1) * 64) * 2;
        const uint32_t A0 = ring[sbase + r0 * 2 + 0];
        const uint32_t A1 = ring[sbase + r0 * 2 + 1];
        const uint32_t B0 = ring[sbase + r1 * 2 + 0];
        const uint32_t B1 = ring[sbase + r1 * 2 + 1];

        // ---- S-pass: acc = x1 . x2^T (hi*hi + hi*lo + lo*hi), 16x64 ----
        float acc[8][4];
#pragma unroll
        for (int i = 0; i < 8; i++)
#pragma unroll
            for (int j = 0; j < 4; j++) acc[i][j] = 0.0f;

#pragma unroll
        for (int ks = 0; ks < 8; ks++) {
            uint32_t ah[4], al[4];
            ldsm_x4(ah, tile_addr(base + SM_X1H, arow, ks * 16 + acol));
            ldsm_x4(al, tile_addr(base + SM_X1L, arow, ks * 16 + acol));
#pragma unroll
            for (int nb = 0; nb < 4; nb++) {
                uint32_t bh[4], bl[4];
                ldsm_x4(bh, tile_addr(X2H, nb * 16 + bro, ks * 16 + bco));
                ldsm_x4(bl, tile_addr(X2L, nb * 16 + bro, ks * 16 + bco));
                mma16816(acc[2 * nb], ah, bh);
                mma16816(acc[2 * nb + 1], ah, bh + 2);
                mma16816(acc[2 * nb], ah, bl);
                mma16816(acc[2 * nb + 1], ah, bl + 2);
                mma16816(acc[2 * nb], al, bh);
                mma16816(acc[2 * nb + 1], al, bh + 2);
            }
        }

        // ---- online softmax: rescale state, exp, mask -> overwrite acc ----
        float tm0 = -INFINITY, tm1 = -INFINITY;
#pragma unroll
        for (int nf = 0; nf < 8; nf++) {
            acc[nf][0] *= SCALE; acc[nf][1] *= SCALE;
            acc[nf][2] *= SCALE; acc[nf][3] *= SCALE;
            tm0 = fmaxf(tm0, fmaxf(acc[nf][0], acc[nf][1]));
            tm1 = fmaxf(tm1, fmaxf(acc[nf][2], acc[nf][3]));
        }
        tm0 = fmaxf(tm0, __shfl_xor_sync(0xffffffffu, tm0, 1));
        tm0 = fmaxf(tm0, __shfl_xor_sync(0xffffffffu, tm0, 2));
        tm1 = fmaxf(tm1, __shfl_xor_sync(0xffffffffu, tm1, 1));
        tm1 = fmaxf(tm1, __shfl_xor_sync(0xffffffffu, tm1, 2));
        const float nm0 = fmaxf(m0, tm0);
        const float nm1 = fmaxf(m1, tm1);
        const float f0 = __expf(m0 - nm0);
        const float f1 = __expf(m1 - nm1);
        m0 = nm0; m1 = nm1;
        l0 *= f0; l1 *= f1;
#pragma unroll
        for (int nf = 0; nf < 16; nf++) {
            O[nf][0] *= f0; O[nf][1] *= f0;
            O[nf][2] *= f1; O[nf][3] *= f1;
        }

#pragma unroll
        for (int nf = 0; nf < 8; nf++) {
            float e0 = __expf(acc[nf][0] - m0);
            float e1 = __expf(acc[nf][1] - m0);
            float e2 = __expf(acc[nf][2] - m1);
            float e3 = __expf(acc[nf][3] - m1);
            l0 += e0 + e1;
            l1 += e2 + e3;
            const int sh = (nf & 3) * 8 + qr;
            unsigned w0 = (nf < 4 ? A0 : A1) >> sh;
            unsigned w1 = (nf < 4 ? B0 : B1) >> sh;
            acc[nf][0] = (w0 & 1u) ? e0 : 0.0f;
            acc[nf][1] = (w0 & 2u) ? e1 : 0.0f;
            acc[nf][2] = (w1 & 1u) ? e2 : 0.0f;
            acc[nf][3] = (w1 & 2u) ? e3 : 0.0f;
        }

        // ---- PV-pass: pack P on the fly, O += P . V (k=64 -> 4 ks) ----
#pragma unroll
        for (int ks = 0; ks < 4; ks++) {
            uint32_t ph[4], pl[4];
#pragma unroll
            for (int h = 0; h < 2; h++) {
                const float* a4 = acc[2 * ks + h];
                uint32_t h0 = pack_bf16(a4[0], a4[1]);
                uint32_t h1 = pack_bf16(a4[2], a4[3]);
                ph[2 * h + 0] = h0;
                ph[2 * h + 1] = h1;
                pl[2 * h + 0] = pack_bf16(a4[0] - __uint_as_float(h0 << 16),
                                          a4[1] - __uint_as_float(h0 & 0xffff0000u));
                pl[2 * h + 1] = pack_bf16(a4[2] - __uint_as_float(h1 << 16),
                                          a4[3] - __uint_as_float(h1 & 0xffff0000u));
            }
#pragma unroll
            for (int nb = 0; nb < 8; nb++) {
                uint32_t vh[4], vl[4];
                ldsm_x4_t(vh, tile_addr(X2H, ks * 16 + vro, nb * 16 + vco));
                ldsm_x4_t(vl, tile_addr(X2L, ks * 16 + vro, nb * 16 + vco));
                mma16816(O[2 * nb], ph, vh);
                mma16816(O[2 * nb + 1], ph, vh + 2);
                mma16816(O[2 * nb], ph, vl);
                mma16816(O[2 * nb + 1], ph, vl + 2);
                mma16816(O[2 * nb], pl, vh);
                mma16816(O[2 * nb + 1], pl, vh + 2);
            }
        }
        BAR_CONS();  // consumers done with X2 buffer + ring slot
        if (tid == 0) *cc = t + 1;
    }

    // ---- epilogue: O / (l * 0.7) ----
    l0 += __shfl_xor_sync(0xffffffffu, l0, 1);
    l0 += __shfl_xor_sync(0xffffffffu, l0, 2);
    l1 += __shfl_xor_sync(0xffffffffu, l1, 1);
    l1 += __shfl_xor_sync(0xffffffffu, l1, 2);
    const float s0 = INV_KEEP / l0;
    const float s1 = INV_KEEP / l1;

    const int rg = bq + w * 16 + (lane >> 2);
    float* C = out + ((size_t)b * NQ + rg) * DIM;
#pragma unroll
    for (int nf = 0; nf < 16; nf++) {
        const int c0 = nf * 8 + qr;
        *(float2*)(C + c0) = make_float2(O[nf][0] * s0, O[nf][1] * s0);
        *(float2*)(C + 8 * DIM + c0) = make_float2(O[nf][2] * s1, O[nf][3] * s1);
    }
}

// ---------------------------------------------------------------------------
extern "C" void kernel_launch(void* const* d_in, const int* in_sizes, int n_in,
                              void* d_out, int out_size) {
    const float* x1 = (const float*)d_in[0];
    const float* x2 = (const float*)d_in[1];
    float* out = (float*)d_out;

    cudaFuncSetAttribute(fused_attn, cudaFuncAttributeMaxDynamicSharedMemorySize, SMEM_BYTES);

    split_kernel<<<(BATCH * NQ * DIM) / 256, 256>>>(x1, x2);
    fused_attn<<<dim3(32, 16), 256, SMEM_BYTES>>>(out);
}